// round 9
// baseline (speedup 1.0000x reference)
#include <cuda_runtime.h>
#include <cuda_bf16.h>
#include <math.h>
#include <cstdint>

// ---------------------------------------------------------------------------
// Problem constants
// ---------------------------------------------------------------------------
namespace {
constexpr int B_FULL  = 2048;
constexpr int N_PIX   = 1024;
constexpr int T_DIV   = 64;
constexpr int C_CLS   = 10;
constexpr int PER_DIV = 16;
constexpr int K_DIM   = 512;          // k = i*4 + m (w_mid memory order)
constexpr int R_RANK  = 128;
constexpr int BT      = 64;           // batch rows per CTA
constexpr int NTHR    = 256;          // 8 warps: 2(m) x 4(n), warp tile m32 x n32

constexpr int PADK    = 520;          // padded k-stride (halves) -> conflict-free ldmatrix

// smem byte offsets
constexpr int OFF_B   = 0;                         // [128][520] bf16 = 133120
constexpr int OFF_A   = OFF_B + R_RANK * PADK * 2; // [64][520] bf16 = 66560
constexpr int OFF_X0  = OFF_A + BT * PADK * 2;     // 64 float4
constexpr int OFF_X1  = OFF_X0 + 1024;             // 64 float4
constexpr int OFF_S0  = OFF_X1 + 1024;             // 128 f32
constexpr int OFF_WL  = OFF_S0 + 512;              // 128 f32
constexpr int OFF_RED = OFF_WL + 512;              // 64*16 f32 = 4096
constexpr int SMEM_BYTES = OFF_RED + 4096;         // 206848
}

// ---------------------------------------------------------------------------
// Device scratch
// ---------------------------------------------------------------------------
__device__ float g_logits[B_FULL * C_CLS];     // [b][c]

// ---------------------------------------------------------------------------
// asm helpers (base-sm_103 legal)
// ---------------------------------------------------------------------------
__device__ __forceinline__ uint32_t smem_to_u32(const void* p) {
    uint32_t a;
    asm("{ .reg .u64 t; cvta.to.shared.u64 t, %1; cvt.u32.u64 %0, t; }" : "=r"(a) : "l"(p));
    return a;
}
__device__ __forceinline__ void ldsm4(uint32_t* r, uint32_t addr) {
    asm volatile("ldmatrix.sync.aligned.m8n8.x4.shared.b16 {%0,%1,%2,%3}, [%4];"
                 : "=r"(r[0]), "=r"(r[1]), "=r"(r[2]), "=r"(r[3]) : "r"(addr));
}
__device__ __forceinline__ void mma16816(float* d, const uint32_t* a, uint32_t b0, uint32_t b1) {
    asm volatile("mma.sync.aligned.m16n8k16.row.col.f32.bf16.bf16.f32 "
                 "{%0,%1,%2,%3}, {%4,%5,%6,%7}, {%8,%9}, {%0,%1,%2,%3};"
                 : "+f"(d[0]), "+f"(d[1]), "+f"(d[2]), "+f"(d[3])
                 : "r"(a[0]), "r"(a[1]), "r"(a[2]), "r"(a[3]), "r"(b0), "r"(b1));
}
__device__ __forceinline__ uint32_t packbf(float hi, float lo) {
    uint32_t u;
    asm("cvt.rn.bf16x2.f32 %0, %1, %2;" : "=r"(u) : "f"(hi), "f"(lo));
    return u;   // memory order: [lo, hi]
}
__device__ __forceinline__ uint32_t mulbf2(uint32_t a, uint32_t b) {
    uint32_t d;
    asm("mul.bf16x2 %0, %1, %2;" : "=r"(d) : "r"(a), "r"(b));
    return d;
}
__device__ __forceinline__ void bar_arrive128(int id) {
    asm volatile("bar.arrive %0, 128;" :: "r"(id) : "memory");
}
__device__ __forceinline__ void bar_sync128(int id) {
    asm volatile("bar.sync %0, 128;" :: "r"(id) : "memory");
}

// ---------------------------------------------------------------------------
// Inline feature map: all 256 threads; row = tid>>2, 4 pixels per thread,
// shfl-reduce over the 4 adjacent lanes; lane pq==0 writes sXn[row].
// ---------------------------------------------------------------------------
__device__ __forceinline__ void compute_x(const float* __restrict__ tensor,
                                          int b0, int t, float4* sXn, int tid) {
    int row = tid >> 2, pq = tid & 3;
    float4 v = *reinterpret_cast<const float4*>(tensor + (b0 + row) * N_PIX + t * PER_DIV + pq * 4);
    float a0 = 0.f, a1 = 0.f, a2 = 0.f, a3 = 0.f;
    float xs[4] = {v.x, v.y, v.z, v.w};
#pragma unroll
    for (int q = 0; q < 4; ++q) {
        float s, c;
        sincosf(1.57079632679489662f * xs[q], &s, &c);
        float c2 = c * c, s2 = s * s;
        a0 += c2 * c; a1 += c2 * s; a2 += c * s2; a3 += s2 * s;
    }
#pragma unroll
    for (int off = 2; off >= 1; off >>= 1) {
        a0 += __shfl_down_sync(0xFFFFFFFF, a0, off);
        a1 += __shfl_down_sync(0xFFFFFFFF, a1, off);
        a2 += __shfl_down_sync(0xFFFFFFFF, a2, off);
        a3 += __shfl_down_sync(0xFFFFFFFF, a3, off);
    }
    const float inv = 1.0f / (float)PER_DIV;
    if (pq == 0) sXn[row] = make_float4(a0 * inv, a1 * inv, a2 * inv, a3 * inv);
}

// ---------------------------------------------------------------------------
// Fused kernel: feature map + TT recurrence (ldmatrix + mma.sync bf16/f32).
// 8 warps 2(m) x 4(n), warp tile m32 x n32.  Per-step skeleton:
//   full-sync -> build OWN A block (rows mg32, cols ng32) -> bar.arrive x3 ->
//   __syncwarp -> GEMM own 8 kt (B frags in regs) -> bar.sync per foreign
//   block -> stream remaining 24 kt.  x_{t+1} recomputed inline during GEMM.
// ---------------------------------------------------------------------------
__global__ __launch_bounds__(NTHR) void rec_hmma_kernel(const float* __restrict__ tensor,
                                                        const float* __restrict__ w_first,
                                                        const float* __restrict__ w_mid,
                                                        const float* __restrict__ w_last) {
    extern __shared__ char smem[];
    const int tid = threadIdx.x;
    const int l   = tid & 31;
    const int wid = tid >> 5;
    const int mg  = wid & 1;      // m-group: rows mg*32 .. mg*32+31
    const int ng  = wid >> 1;     // n-group: cols ng*32 .. ng*32+31 (0..3)
    const int c   = blockIdx.y;
    const int b0  = blockIdx.x * BT;

    const uint32_t smem_u = smem_to_u32(smem);
    __nv_bfloat16* sB = reinterpret_cast<__nv_bfloat16*>(smem + OFF_B);
    float*  s0s  = reinterpret_cast<float*>(smem + OFF_S0);
    float*  wls  = reinterpret_cast<float*>(smem + OFF_WL);
    float4* sX0  = reinterpret_cast<float4*>(smem + OFF_X0);
    float4* sX1  = reinterpret_cast<float4*>(smem + OFF_X1);
    float*  sRed = reinterpret_cast<float*>(smem + OFF_RED);

    // ---- stage weights: sB[o][k] = bf16(w_mid[c, k, o]), padded stride ----
    {
        const float* Wc = w_mid + c * (K_DIM * R_RANK);
        for (int q = tid; q < K_DIM * R_RANK / 4; q += NTHR) {
            int k = q >> 5;
            int j = (q & 31) << 2;
            float4 v = *reinterpret_cast<const float4*>(Wc + k * R_RANK + j);
            sB[(j + 0) * PADK + k] = __float2bfloat16(v.x);
            sB[(j + 1) * PADK + k] = __float2bfloat16(v.y);
            sB[(j + 2) * PADK + k] = __float2bfloat16(v.z);
            sB[(j + 3) * PADK + k] = __float2bfloat16(v.w);
        }
    }
    if (tid < R_RANK) {
        const float* wf = w_first + c * 512;
        s0s[tid] = wf[tid] + wf[128 + tid] + wf[256 + tid] + wf[384 + tid];
        const float* wl = w_last + c * 512;
        wls[tid] = wl[4 * tid] + wl[4 * tid + 1] + wl[4 * tid + 2] + wl[4 * tid + 3];
    }
    compute_x(tensor, b0, 0, sX0, tid);
    __syncthreads();

    // ldmatrix address bases (bytes), canonical x4 lane->row mapping
    uint32_t aBase[2], bBase[2];
#pragma unroll
    for (int mt = 0; mt < 2; ++mt)
        aBase[mt] = smem_u + OFF_A +
            (((mg * 32 + mt * 16 + (l & 7) + ((l >> 3) & 1) * 8) * PADK + (l >> 4) * 8) << 1);
#pragma unroll
    for (int p = 0; p < 2; ++p)
        bBase[p] = smem_u + OFF_B +
            (((ng * 32 + p * 16 + (l >> 4) * 8 + (l & 7)) * PADK + ((l >> 3) & 1) * 8) << 1);

    // own-block B fragments (kt = ng*8 .. ng*8+7) persist in registers
    const int kt0 = ng * 8;
    uint32_t Bp[8][2][4];
#pragma unroll
    for (int j = 0; j < 8; ++j) {
        ldsm4(Bp[j][0], bBase[0] + (kt0 + j) * 32);
        ldsm4(Bp[j][1], bBase[1] + (kt0 + j) * 32);
    }

    float acc[2][4][4];
    const int g  = l >> 2;     // row within 8-group
    const int cc = l & 3;      // col pair selector

    // GEMM block helpers -----------------------------------------------------
    auto gemm_own = [&]() {
        uint32_t Af[2][2][4];
        ldsm4(Af[0][0], aBase[0] + kt0 * 32);
        ldsm4(Af[0][1], aBase[1] + kt0 * 32);
#pragma unroll
        for (int j = 0; j < 8; ++j) {
            int cur = j & 1, nx = cur ^ 1;
            if (j < 7) {
                ldsm4(Af[nx][0], aBase[0] + (kt0 + j + 1) * 32);
                ldsm4(Af[nx][1], aBase[1] + (kt0 + j + 1) * 32);
            }
#pragma unroll
            for (int nt = 0; nt < 4; ++nt) {
                uint32_t b0v = Bp[j][nt >> 1][(nt & 1) * 2];
                uint32_t b1v = Bp[j][nt >> 1][(nt & 1) * 2 + 1];
                mma16816(acc[0][nt], Af[cur][0], b0v, b1v);
                mma16816(acc[1][nt], Af[cur][1], b0v, b1v);
            }
        }
    };
    auto gemm_foreign = [&](int kb) {   // kb = first kt of an 8-kt block
        uint32_t Af[2][2][4], Bf[2][2][4];
        ldsm4(Af[0][0], aBase[0] + kb * 32);
        ldsm4(Af[0][1], aBase[1] + kb * 32);
        ldsm4(Bf[0][0], bBase[0] + kb * 32);
        ldsm4(Bf[0][1], bBase[1] + kb * 32);
#pragma unroll
        for (int j = 0; j < 8; ++j) {
            int cur = j & 1, nx = cur ^ 1;
            if (j < 7) {
                ldsm4(Af[nx][0], aBase[0] + (kb + j + 1) * 32);
                ldsm4(Af[nx][1], aBase[1] + (kb + j + 1) * 32);
                ldsm4(Bf[nx][0], bBase[0] + (kb + j + 1) * 32);
                ldsm4(Bf[nx][1], bBase[1] + (kb + j + 1) * 32);
            }
#pragma unroll
            for (int nt = 0; nt < 4; ++nt) {
                uint32_t b0v = Bf[cur][nt >> 1][(nt & 1) * 2];
                uint32_t b1v = Bf[cur][nt >> 1][(nt & 1) * 2 + 1];
                mma16816(acc[0][nt], Af[cur][0], b0v, b1v);
                mma16816(acc[1][nt], Af[cur][1], b0v, b1v);
            }
        }
    };
    auto zero_acc = [&]() {
#pragma unroll
        for (int mt = 0; mt < 2; ++mt)
#pragma unroll
            for (int nt = 0; nt < 4; ++nt)
#pragma unroll
                for (int q = 0; q < 4; ++q) acc[mt][nt][q] = 0.f;
    };

    // ---- t = 0: build full A from s0 (scattered threads), full sync --------
    {
        int i  = tid & 127;
        int bh = tid >> 7;
        float s = s0s[i];
        for (int b = bh * 32; b < bh * 32 + 32; ++b) {
            float4 x = sX0[b];
            uint2 u;
            u.x = packbf(s * x.y, s * x.x);
            u.y = packbf(s * x.w, s * x.z);
            *reinterpret_cast<uint2*>(smem + OFF_A + ((b * PADK + 4 * i) << 1)) = u;
        }
    }
    __syncthreads();
    zero_acc();
    gemm_own();
    compute_x(tensor, b0, 1, sX1, tid);          // x for t=1, overlapped
    gemm_foreign((kt0 + 8)  & 31);
    gemm_foreign((kt0 + 16) & 31);
    gemm_foreign((kt0 + 24) & 31);

    // ---- steps t = 1 .. 63 -------------------------------------------------
    for (int t = 1; t < T_DIV; ++t) {
        float4* sXc = (t & 1) ? sX1 : sX0;
        float4* sXn = (t & 1) ? sX0 : sX1;
        __syncthreads();   // all GEMM reads of sA done; sXc complete

        // build OWN A block: rows [mg*32, +32), cols i in [ng*32, +32)
#pragma unroll
        for (int mt = 0; mt < 2; ++mt) {
            int r = mg * 32 + mt * 16 + g;
            float4 xa = sXc[r];
            float4 xb = sXc[r + 8];
            uint32_t xa01 = packbf(xa.y, xa.x), xa23 = packbf(xa.w, xa.z);
            uint32_t xb01 = packbf(xb.y, xb.x), xb23 = packbf(xb.w, xb.z);
#pragma unroll
            for (int nt = 0; nt < 4; ++nt) {
                int i0 = ng * 32 + nt * 8 + 2 * cc;
                uint32_t s0p = packbf(acc[mt][nt][0], acc[mt][nt][0]);
                uint32_t s1p = packbf(acc[mt][nt][1], acc[mt][nt][1]);
                uint32_t s2p = packbf(acc[mt][nt][2], acc[mt][nt][2]);
                uint32_t s3p = packbf(acc[mt][nt][3], acc[mt][nt][3]);
                uint4 ua, ub;
                ua.x = mulbf2(s0p, xa01); ua.y = mulbf2(s0p, xa23);
                ua.z = mulbf2(s1p, xa01); ua.w = mulbf2(s1p, xa23);
                *reinterpret_cast<uint4*>(smem + OFF_A + ((r * PADK + 4 * i0) << 1)) = ua;
                ub.x = mulbf2(s2p, xb01); ub.y = mulbf2(s2p, xb23);
                ub.z = mulbf2(s3p, xb01); ub.w = mulbf2(s3p, xb23);
                *reinterpret_cast<uint4*>(smem + OFF_A + (((r + 8) * PADK + 4 * i0) << 1)) = ub;
            }
        }
        // announce our block (id = 4*producer + consumer, counts 64+64)
#pragma unroll
        for (int d = 1; d < 4; ++d) bar_arrive128(ng * 4 + ((ng + d) & 3));
        __syncwarp();      // own block fully written by this warp itself

        zero_acc();
        gemm_own();
        if (t < T_DIV - 1) compute_x(tensor, b0, t + 1, sXn, tid);
#pragma unroll
        for (int d = 1; d < 4; ++d) {
            int q = (ng + d) & 3;                // foreign block producer pair
            bar_sync128(q * 4 + ng);
            gemm_foreign(q * 8);
        }
    }

    // ---- final projection: logits[b] = dot(state_b, wl) ----
#pragma unroll
    for (int mt = 0; mt < 2; ++mt) {
        int r = mg * 32 + mt * 16 + g;
        float p0 = 0.f, p1 = 0.f;
#pragma unroll
        for (int nt = 0; nt < 4; ++nt) {
            int i0 = ng * 32 + nt * 8 + 2 * cc;
            float w0 = wls[i0], w1 = wls[i0 + 1];
            p0 += acc[mt][nt][0] * w0 + acc[mt][nt][1] * w1;
            p1 += acc[mt][nt][2] * w0 + acc[mt][nt][3] * w1;
        }
        sRed[r * 16 + ng * 4 + cc]       = p0;
        sRed[(r + 8) * 16 + ng * 4 + cc] = p1;
    }
    __syncthreads();
    if (tid < BT) {
        float sum = 0.f;
#pragma unroll
        for (int q = 0; q < 16; ++q) sum += sRed[tid * 16 + q];
        g_logits[(b0 + tid) * C_CLS + c] = sum;
    }
}

// ---------------------------------------------------------------------------
// log_softmax over C=10
// ---------------------------------------------------------------------------
__global__ void lsm_kernel(float* __restrict__ out) {
    int b = blockIdx.x * blockDim.x + threadIdx.x;
    if (b >= B_FULL) return;
    float v[C_CLS];
    float mx = -INFINITY;
#pragma unroll
    for (int c = 0; c < C_CLS; ++c) {
        v[c] = g_logits[b * C_CLS + c];
        mx = fmaxf(mx, v[c]);
    }
    float s = 0.f;
#pragma unroll
    for (int c = 0; c < C_CLS; ++c) s += expf(v[c] - mx);
    float lg = mx + logf(s);
#pragma unroll
    for (int c = 0; c < C_CLS; ++c) out[b * C_CLS + c] = v[c] - lg;
}

// ---------------------------------------------------------------------------
// Entry point
// ---------------------------------------------------------------------------
extern "C" void kernel_launch(void* const* d_in, const int* in_sizes, int n_in,
                              void* d_out, int out_size) {
    const float* tensor  = (const float*)d_in[0];   // (2048, 1024)
    const float* w_first = (const float*)d_in[1];   // (10, 1, 4, 128)
    const float* w_mid   = (const float*)d_in[2];   // (10, 128, 4, 128)
    const float* w_last  = (const float*)d_in[3];   // (10, 128, 4, 1)
    float* out = (float*)d_out;                     // (2048, 10)

    cudaFuncSetAttribute(rec_hmma_kernel, cudaFuncAttributeMaxDynamicSharedMemorySize, SMEM_BYTES);

    rec_hmma_kernel<<<dim3(B_FULL / BT, C_CLS), NTHR, SMEM_BYTES>>>(tensor, w_first, w_mid, w_last);
    lsm_kernel<<<(B_FULL + 255) / 256, 256>>>(out);
}

// round 10
// speedup vs baseline: 1.1655x; 1.1655x over previous
#include <cuda_runtime.h>
#include <cuda_bf16.h>
#include <math.h>
#include <cstdint>

// ---------------------------------------------------------------------------
// Problem constants
// ---------------------------------------------------------------------------
namespace {
constexpr int B_FULL  = 2048;
constexpr int N_PIX   = 1024;
constexpr int T_DIV   = 64;
constexpr int C_CLS   = 10;
constexpr int PER_DIV = 16;
constexpr int K_DIM   = 512;          // k = i*4 + m (w_mid memory order)
constexpr int R_RANK  = 128;
constexpr int BT      = 64;           // batch rows per CTA
constexpr int NTHR    = 256;          // 8 warps: 2(m) x 4(n), warp tile m32 x n32
constexpr int NB      = 16;           // k-tiles whose B fragments persist in registers

constexpr int PADK    = 520;          // padded k-stride (halves) -> conflict-free ldmatrix

// smem byte offsets
constexpr int OFF_B   = 0;                         // [128][520] bf16 = 133120
constexpr int OFF_A   = OFF_B + R_RANK * PADK * 2; // [64][520] bf16 = 66560
constexpr int OFF_X   = OFF_A + BT * PADK * 2;     // 64 float4 = 1024
constexpr int OFF_S0  = OFF_X + 1024;              // 128 f32
constexpr int OFF_WL  = OFF_S0 + 512;              // 128 f32
constexpr int OFF_RED = OFF_WL + 512;              // 64*16 f32 = 4096
constexpr int SMEM_BYTES = OFF_RED + 4096;         // 205824
}

// ---------------------------------------------------------------------------
// Device scratch
// ---------------------------------------------------------------------------
__device__ float4 g_div4[T_DIV * B_FULL];      // [t][b] -> M=4 features
__device__ float  g_logits[B_FULL * C_CLS];    // [b][c]

// ---------------------------------------------------------------------------
// asm helpers (base-sm_103 legal)
// ---------------------------------------------------------------------------
__device__ __forceinline__ uint32_t smem_to_u32(const void* p) {
    uint32_t a;
    asm("{ .reg .u64 t; cvta.to.shared.u64 t, %1; cvt.u32.u64 %0, t; }" : "=r"(a) : "l"(p));
    return a;
}
__device__ __forceinline__ void ldsm4(uint32_t* r, uint32_t addr) {
    asm volatile("ldmatrix.sync.aligned.m8n8.x4.shared.b16 {%0,%1,%2,%3}, [%4];"
                 : "=r"(r[0]), "=r"(r[1]), "=r"(r[2]), "=r"(r[3]) : "r"(addr));
}
__device__ __forceinline__ void mma16816(float* d, const uint32_t* a, uint32_t b0, uint32_t b1) {
    asm volatile("mma.sync.aligned.m16n8k16.row.col.f32.bf16.bf16.f32 "
                 "{%0,%1,%2,%3}, {%4,%5,%6,%7}, {%8,%9}, {%0,%1,%2,%3};"
                 : "+f"(d[0]), "+f"(d[1]), "+f"(d[2]), "+f"(d[3])
                 : "r"(a[0]), "r"(a[1]), "r"(a[2]), "r"(a[3]), "r"(b0), "r"(b1));
}
__device__ __forceinline__ uint32_t packbf(float hi, float lo) {
    uint32_t u;
    asm("cvt.rn.bf16x2.f32 %0, %1, %2;" : "=r"(u) : "f"(hi), "f"(lo));
    return u;   // memory order: [lo, hi]
}
__device__ __forceinline__ uint32_t mulbf2(uint32_t a, uint32_t b) {
    uint32_t d;
    asm("mul.bf16x2 %0, %1, %2;" : "=r"(d) : "r"(a), "r"(b));
    return d;
}

// ---------------------------------------------------------------------------
// Kernel 1: feature map + division averaging
// ---------------------------------------------------------------------------
__global__ void feat_kernel(const float* __restrict__ tensor) {
    int idx = blockIdx.x * blockDim.x + threadIdx.x;
    if (idx >= B_FULL * T_DIV) return;
    int b = idx >> 6;
    int t = idx & (T_DIV - 1);
    const float4* p = reinterpret_cast<const float4*>(tensor + b * N_PIX + t * PER_DIV);
    float a0 = 0.f, a1 = 0.f, a2 = 0.f, a3 = 0.f;
#pragma unroll
    for (int j = 0; j < 4; ++j) {
        float4 v = p[j];
        float xs[4] = {v.x, v.y, v.z, v.w};
#pragma unroll
        for (int q = 0; q < 4; ++q) {
            float ang = 1.57079632679489662f * xs[q];
            float s, c;
            sincosf(ang, &s, &c);
            float c2 = c * c, s2 = s * s;
            a0 += c2 * c; a1 += c2 * s; a2 += c * s2; a3 += s2 * s;
        }
    }
    const float inv = 1.0f / (float)PER_DIV;
    g_div4[t * B_FULL + b] = make_float4(a0 * inv, a1 * inv, a2 * inv, a3 * inv);
}

// ---------------------------------------------------------------------------
// Kernel 2: TT recurrence via ldmatrix + mma.sync (bf16, fp32 accum).
// R8 skeleton (best known): flat per-step  sync -> A-build -> sync -> GEMM,
// with NB=16 B k-tiles persistent in registers and x_t prefetched in regs.
// ---------------------------------------------------------------------------
__global__ __launch_bounds__(NTHR) void rec_hmma_kernel(const float* __restrict__ w_first,
                                                        const float* __restrict__ w_mid,
                                                        const float* __restrict__ w_last) {
    extern __shared__ char smem[];
    const int tid = threadIdx.x;
    const int l   = tid & 31;
    const int wid = tid >> 5;
    const int mg  = wid & 1;      // m-group: rows mg*32 .. mg*32+31
    const int ng  = wid >> 1;     // n-group: cols ng*32 .. ng*32+31 (0..3)
    const int c   = blockIdx.y;
    const int b0  = blockIdx.x * BT;

    const uint32_t smem_u = smem_to_u32(smem);
    __nv_bfloat16* sB = reinterpret_cast<__nv_bfloat16*>(smem + OFF_B);
    float*  s0s  = reinterpret_cast<float*>(smem + OFF_S0);
    float*  wls  = reinterpret_cast<float*>(smem + OFF_WL);
    float4* sX   = reinterpret_cast<float4*>(smem + OFF_X);
    float*  sRed = reinterpret_cast<float*>(smem + OFF_RED);

    // ---- stage weights: sB[o][k] = bf16(w_mid[c, k, o]), padded stride ----
    {
        const float* Wc = w_mid + c * (K_DIM * R_RANK);
        for (int q = tid; q < K_DIM * R_RANK / 4; q += NTHR) {
            int k = q >> 5;
            int j = (q & 31) << 2;
            float4 v = *reinterpret_cast<const float4*>(Wc + k * R_RANK + j);
            sB[(j + 0) * PADK + k] = __float2bfloat16(v.x);
            sB[(j + 1) * PADK + k] = __float2bfloat16(v.y);
            sB[(j + 2) * PADK + k] = __float2bfloat16(v.z);
            sB[(j + 3) * PADK + k] = __float2bfloat16(v.w);
        }
    }
    // ---- s0[o] = sum_m w_first[c,0,m,o]; wl[o] = sum_m w_last[c,o,m] ----
    if (tid < R_RANK) {
        const float* wf = w_first + c * 512;
        s0s[tid] = wf[tid] + wf[128 + tid] + wf[256 + tid] + wf[384 + tid];
        const float* wl = w_last + c * 512;
        wls[tid] = wl[4 * tid] + wl[4 * tid + 1] + wl[4 * tid + 2] + wl[4 * tid + 3];
    }
    __syncthreads();

    // ldmatrix address bases (bytes), canonical x4 lane->row mapping
    uint32_t aBase[2], bBase[2];
#pragma unroll
    for (int mt = 0; mt < 2; ++mt)
        aBase[mt] = smem_u + OFF_A +
            (((mg * 32 + mt * 16 + (l & 7) + ((l >> 3) & 1) * 8) * PADK + (l >> 4) * 8) << 1);
#pragma unroll
    for (int p = 0; p < 2; ++p)
        bBase[p] = smem_u + OFF_B +
            (((ng * 32 + p * 16 + (l >> 4) * 8 + (l & 7)) * PADK + ((l >> 3) & 1) * 8) << 1);

    // ---- persistent B fragments for kt 0..NB-1 (B is step-invariant) ----
    uint32_t Bp[NB][2][4];
#pragma unroll
    for (int kt = 0; kt < NB; ++kt) {
        ldsm4(Bp[kt][0], bBase[0] + kt * 32);
        ldsm4(Bp[kt][1], bBase[1] + kt * 32);
    }

    float acc[2][4][4];
    const int g  = l >> 2;     // row within 8-group
    const int cc = l & 3;      // col pair selector

    float4 gx = make_float4(0.f, 0.f, 0.f, 0.f);
    if (tid < BT) gx = g_div4[b0 + tid];   // t = 0

    for (int t = 0; t < T_DIV; ++t) {
        if (tid < BT) sX[tid] = gx;
        __syncthreads();   // sX ready; previous step's mma done reading sA

        if (t == 0) {
            // A[b, 4i+m] = bf16(s0[i] * x[b][m]); thread owns i = tid&127
            int i  = tid & 127;
            int bh = tid >> 7;
            float s = s0s[i];
            for (int b = bh * 32; b < bh * 32 + 32; ++b) {
                float4 x = sX[b];
                uint2 u;
                u.x = packbf(s * x.y, s * x.x);
                u.y = packbf(s * x.w, s * x.z);
                *reinterpret_cast<uint2*>(smem + OFF_A + ((b * PADK + 4 * i) << 1)) = u;
            }
        } else {
            // convert this warp's D fragments into A via bf16x2 HMUL2
#pragma unroll
            for (int mt = 0; mt < 2; ++mt) {
                int r = mg * 32 + mt * 16 + g;
                float4 xa = sX[r];
                float4 xb = sX[r + 8];
                uint32_t xa01 = packbf(xa.y, xa.x), xa23 = packbf(xa.w, xa.z);
                uint32_t xb01 = packbf(xb.y, xb.x), xb23 = packbf(xb.w, xb.z);
#pragma unroll
                for (int nt = 0; nt < 4; ++nt) {
                    int i0 = ng * 32 + nt * 8 + 2 * cc;
                    uint32_t s0p = packbf(acc[mt][nt][0], acc[mt][nt][0]);
                    uint32_t s1p = packbf(acc[mt][nt][1], acc[mt][nt][1]);
                    uint32_t s2p = packbf(acc[mt][nt][2], acc[mt][nt][2]);
                    uint32_t s3p = packbf(acc[mt][nt][3], acc[mt][nt][3]);
                    uint4 ua, ub;
                    ua.x = mulbf2(s0p, xa01); ua.y = mulbf2(s0p, xa23);
                    ua.z = mulbf2(s1p, xa01); ua.w = mulbf2(s1p, xa23);
                    *reinterpret_cast<uint4*>(smem + OFF_A + ((r * PADK + 4 * i0) << 1)) = ua;
                    ub.x = mulbf2(s2p, xb01); ub.y = mulbf2(s2p, xb23);
                    ub.z = mulbf2(s3p, xb01); ub.w = mulbf2(s3p, xb23);
                    *reinterpret_cast<uint4*>(smem + OFF_A + (((r + 8) * PADK + 4 * i0) << 1)) = ub;
                }
            }
        }
#pragma unroll
        for (int mt = 0; mt < 2; ++mt)
#pragma unroll
            for (int nt = 0; nt < 4; ++nt)
#pragma unroll
                for (int q = 0; q < 4; ++q) acc[mt][nt][q] = 0.f;
        __syncthreads();   // sA fully built

        // prefetch next step's x during the GEMM (off the critical path)
        if (tid < BT && t + 1 < T_DIV) gx = g_div4[(t + 1) * B_FULL + b0 + tid];

        // ---- GEMM: section 1 (kt < NB): B from registers, only A ldsm ----
        uint32_t Af[2][2][4], Bf[2][2][4];
        ldsm4(Af[0][0], aBase[0]);
        ldsm4(Af[0][1], aBase[1]);
        ldsm4(Bf[NB & 1][0], bBase[0] + NB * 32);   // preload B for kt=NB
        ldsm4(Bf[NB & 1][1], bBase[1] + NB * 32);
#pragma unroll
        for (int kt = 0; kt < NB; ++kt) {
            int cur = kt & 1, nx = cur ^ 1;
            ldsm4(Af[nx][0], aBase[0] + (kt + 1) * 32);
            ldsm4(Af[nx][1], aBase[1] + (kt + 1) * 32);
#pragma unroll
            for (int nt = 0; nt < 4; ++nt) {
                uint32_t b0v = Bp[kt][nt >> 1][(nt & 1) * 2];
                uint32_t b1v = Bp[kt][nt >> 1][(nt & 1) * 2 + 1];
                mma16816(acc[0][nt], Af[cur][0], b0v, b1v);
                mma16816(acc[1][nt], Af[cur][1], b0v, b1v);
            }
        }
        // ---- section 2 (kt = NB..31): double-buffered A and B ----
#pragma unroll
        for (int kt = NB; kt < 32; ++kt) {
            int cur = kt & 1, nx = cur ^ 1;
            if (kt < 31) {
                ldsm4(Af[nx][0], aBase[0] + (kt + 1) * 32);
                ldsm4(Af[nx][1], aBase[1] + (kt + 1) * 32);
                ldsm4(Bf[nx][0], bBase[0] + (kt + 1) * 32);
                ldsm4(Bf[nx][1], bBase[1] + (kt + 1) * 32);
            }
#pragma unroll
            for (int nt = 0; nt < 4; ++nt) {
                uint32_t b0v = Bf[cur][nt >> 1][(nt & 1) * 2];
                uint32_t b1v = Bf[cur][nt >> 1][(nt & 1) * 2 + 1];
                mma16816(acc[0][nt], Af[cur][0], b0v, b1v);
                mma16816(acc[1][nt], Af[cur][1], b0v, b1v);
            }
        }
    }

    // ---- final projection: logits[b] = dot(state_b, wl) ----
#pragma unroll
    for (int mt = 0; mt < 2; ++mt) {
        int r = mg * 32 + mt * 16 + g;
        float p0 = 0.f, p1 = 0.f;
#pragma unroll
        for (int nt = 0; nt < 4; ++nt) {
            int i0 = ng * 32 + nt * 8 + 2 * cc;
            float w0 = wls[i0], w1 = wls[i0 + 1];
            p0 += acc[mt][nt][0] * w0 + acc[mt][nt][1] * w1;
            p1 += acc[mt][nt][2] * w0 + acc[mt][nt][3] * w1;
        }
        sRed[r * 16 + ng * 4 + cc]       = p0;
        sRed[(r + 8) * 16 + ng * 4 + cc] = p1;
    }
    __syncthreads();
    if (tid < BT) {
        float sum = 0.f;
#pragma unroll
        for (int q = 0; q < 16; ++q) sum += sRed[tid * 16 + q];
        g_logits[(b0 + tid) * C_CLS + c] = sum;
    }
}

// ---------------------------------------------------------------------------
// Kernel 3: log_softmax over C=10
// ---------------------------------------------------------------------------
__global__ void lsm_kernel(float* __restrict__ out) {
    int b = blockIdx.x * blockDim.x + threadIdx.x;
    if (b >= B_FULL) return;
    float v[C_CLS];
    float mx = -INFINITY;
#pragma unroll
    for (int c = 0; c < C_CLS; ++c) {
        v[c] = g_logits[b * C_CLS + c];
        mx = fmaxf(mx, v[c]);
    }
    float s = 0.f;
#pragma unroll
    for (int c = 0; c < C_CLS; ++c) s += expf(v[c] - mx);
    float lg = mx + logf(s);
#pragma unroll
    for (int c = 0; c < C_CLS; ++c) out[b * C_CLS + c] = v[c] - lg;
}

// ---------------------------------------------------------------------------
// Dummy kernel: pads the per-iteration launch count to 4 so ncu's fixed
// "-s 5" skip lands on rec_hmma_kernel (5 mod 4 == 1 == rec).
// ---------------------------------------------------------------------------
__global__ void pad_kernel() {}

// ---------------------------------------------------------------------------
// Entry point
// ---------------------------------------------------------------------------
extern "C" void kernel_launch(void* const* d_in, const int* in_sizes, int n_in,
                              void* d_out, int out_size) {
    const float* tensor  = (const float*)d_in[0];   // (2048, 1024)
    const float* w_first = (const float*)d_in[1];   // (10, 1, 4, 128)
    const float* w_mid   = (const float*)d_in[2];   // (10, 128, 4, 128)
    const float* w_last  = (const float*)d_in[3];   // (10, 128, 4, 1)
    float* out = (float*)d_out;                     // (2048, 10)

    cudaFuncSetAttribute(rec_hmma_kernel, cudaFuncAttributeMaxDynamicSharedMemorySize, SMEM_BYTES);

    feat_kernel<<<(B_FULL * T_DIV) / 256, 256>>>(tensor);
    rec_hmma_kernel<<<dim3(B_FULL / BT, C_CLS), NTHR, SMEM_BYTES>>>(w_first, w_mid, w_last);
    lsm_kernel<<<(B_FULL + 255) / 256, 256>>>(out);
    pad_kernel<<<1, 32>>>();
}